// round 6
// baseline (speedup 1.0000x reference)
#include <cuda_runtime.h>
#include <cuda_bf16.h>
#include <stdint.h>

#define B_ 64
#define F_ 4
#define V_ 256
#define D_ 16384
#define ITERS_ 10
#define KCH 32               // split-K chunks for stage 2
#define KC (D_/KCH)          // 512 k per chunk

// ---------------- static device scratch (no runtime allocation) ----------------
__device__ __align__(16) __nv_bfloat16 g_in_bf [B_*D_];                 // input, +-1 bf16
__device__ __align__(16) __nv_bfloat16 g_est_bf[B_*F_*D_];              // current estimates, +-1 bf16
__device__ __align__(16) __nv_bfloat16 g_T_bf  [B_*D_];                 // input * prod_f est (+-1 bf16)
__device__ __align__(16) __nv_bfloat16 g_cbK   [(size_t)F_*V_*D_];      // codebook [f][v][d] bf16
__device__ __align__(16) __nv_bfloat16 g_cbD   [(size_t)F_*D_*V_];      // codebook [f][d][v] bf16 (transposed)
__device__ __align__(16) float         g_simp  [(size_t)KCH*F_*B_*V_];  // split-K partials
__device__ __align__(16) float         g_sim   [F_*B_*V_];              // reduced sim (exact ints)
__device__ __align__(16) __nv_bfloat16 g_Ah    [F_*B_*V_];              // sim & ~127 (exact in bf16)
__device__ __align__(16) __nv_bfloat16 g_Al    [F_*B_*V_];              // sim &  127 (exact in bf16)

// ---------------- mma.sync helper (bf16, fp32 accum — exact for our integer data) ----
__device__ __forceinline__ void mma16816(float c[4], const uint32_t a[4], const uint32_t b[2]) {
    asm volatile(
        "mma.sync.aligned.m16n8k16.row.col.f32.bf16.bf16.f32 "
        "{%0,%1,%2,%3},{%4,%5,%6,%7},{%8,%9},{%0,%1,%2,%3};\n"
        : "+f"(c[0]), "+f"(c[1]), "+f"(c[2]), "+f"(c[3])
        : "r"(a[0]), "r"(a[1]), "r"(a[2]), "r"(a[3]), "r"(b[0]), "r"(b[1]));
}

// ---------------- conversion kernels (run every launch; deterministic) ----------------
// float(+-1) pairs -> packed bf16x2 (+-1). which: 0=g_in_bf, 1=g_est_bf, 2=g_cbK
__global__ void k_sign_pairs(const float* __restrict__ src, int which, int npairs) {
    int i = blockIdx.x * blockDim.x + threadIdx.x;
    if (i >= npairs) return;
    uint2 u = ((const uint2*)src)[i];
    uint32_t w = 0x3F803F80u | ((u.x >> 16) & 0x8000u) | (u.y & 0x80000000u);
    uint32_t* dst = (which == 0) ? (uint32_t*)g_in_bf
                  : (which == 1) ? (uint32_t*)g_est_bf
                                 : (uint32_t*)g_cbK;
    dst[i] = w;
}

// transpose codebook: [f][v][d] float -> [f][d][v] bf16 (+-1)
__global__ void k_trans(const float* __restrict__ cb) {
    __shared__ unsigned short ts[32][33];
    int f = blockIdx.z, d0 = blockIdx.x * 32, v0 = blockIdx.y * 32;
    int tx = threadIdx.x & 31, ty = threadIdx.x >> 5;  // 32 x 8
#pragma unroll
    for (int r = 0; r < 4; r++) {
        int v = v0 + ty + r * 8;
        uint32_t ub = __float_as_uint(cb[((size_t)(f * V_ + v)) * D_ + d0 + tx]);
        ts[ty + r * 8][tx] = (unsigned short)(0x3F80u | ((ub >> 16) & 0x8000u));
    }
    __syncthreads();
#pragma unroll
    for (int r = 0; r < 4; r++) {
        int d = d0 + ty + r * 8;
        ((unsigned short*)g_cbD)[((size_t)(f * D_ + d)) * V_ + v0 + tx] = ts[tx][ty + r * 8];
    }
}

// ---------------- per-iter: T = input * est0 * est1 * est2 * est3 (bf16 XOR) -----------
// XOR of 5 valid +-1 bf16 words keeps magnitude bits 0x3F80 (XORed odd # of times) and
// composes sign bits -> result is a VALID +-1 bf16 word, stored directly.
__global__ void k_totalbf() {
    int i = blockIdx.x * blockDim.x + threadIdx.x;     // uint4 over B_*D_ bf16 elements
    int e0 = i * 8;                                    // element base
    int b = e0 / D_, d = e0 % D_;
    uint4 t = *(const uint4*)(g_in_bf + (size_t)b * D_ + d);
#pragma unroll
    for (int ff = 0; ff < F_; ff++) {
        uint4 e = *(const uint4*)(g_est_bf + ((size_t)b * F_ + ff) * D_ + d);
        t.x ^= e.x; t.y ^= e.y; t.z ^= e.z; t.w ^= e.w;
    }
    *(uint4*)(g_T_bf + (size_t)b * D_ + d) = t;
}

// ---------------- stage 2: sim[f][b][v] = sum_d n[b,f,d] * cb[f,v,d] ----------------
// mode 0: n = T ^ est_f (bipolar product via sign XOR; magnitudes cancel, restored below)
// mode 1: n = est_f (final similarity pass)
__global__ void __launch_bounds__(256) k_sim(int mode) {
    __shared__ __align__(16) __nv_bfloat16 As[64 * 72];
    __shared__ __align__(16) __nv_bfloat16 Bs[256 * 72];
    const int kc = blockIdx.x, f = blockIdx.y;
    const int tid = threadIdx.x;
    const int w = tid >> 5, lane = tid & 31, g = lane >> 2, t = lane & 3;
    const int arow = tid >> 2, aseg = tid & 3;

    float acc[4][4][4];
#pragma unroll
    for (int mt = 0; mt < 4; mt++)
#pragma unroll
        for (int nt = 0; nt < 4; nt++)
#pragma unroll
            for (int j = 0; j < 4; j++) acc[mt][nt][j] = 0.f;

    for (int ks = 0; ks < KC / 64; ks++) {
        const int k0 = kc * KC + ks * 64;
        // --- expand A tile (64 rows x 64 k) ---
        {
            const int kk = k0 + aseg * 16;
            uint4 o0, o1;
            const uint4* pe = (const uint4*)(g_est_bf + ((size_t)arow * F_ + f) * D_ + kk);
            if (mode == 0) {
                const uint4* pt = (const uint4*)(g_T_bf + (size_t)arow * D_ + kk);
                uint4 x0 = pt[0], x1 = pt[1];
                uint4 e0 = pe[0], e1 = pe[1];
                x0.x ^= e0.x; x0.y ^= e0.y; x0.z ^= e0.z; x0.w ^= e0.w;
                x1.x ^= e1.x; x1.y ^= e1.y; x1.z ^= e1.z; x1.w ^= e1.w;
                // magnitude bits of the 2 bf16 words cancel; restore 0x3F80 pattern
                o0.x = 0x3F803F80u ^ x0.x; o0.y = 0x3F803F80u ^ x0.y;
                o0.z = 0x3F803F80u ^ x0.z; o0.w = 0x3F803F80u ^ x0.w;
                o1.x = 0x3F803F80u ^ x1.x; o1.y = 0x3F803F80u ^ x1.y;
                o1.z = 0x3F803F80u ^ x1.z; o1.w = 0x3F803F80u ^ x1.w;
            } else {
                o0 = pe[0]; o1 = pe[1];
            }
            uint4* as = (uint4*)((uint32_t*)As + arow * 36 + aseg * 8);
            as[0] = o0; as[1] = o1;
        }
        // --- load B tile (256 v x 64 k) ---
#pragma unroll
        for (int p = 0; p < 8; p++) {
            int v = p * 32 + (tid >> 3); int ch = tid & 7;
            const uint4* pb = (const uint4*)(g_cbK + ((size_t)(f * V_ + v)) * D_ + k0 + ch * 8);
            *(uint4*)((uint32_t*)Bs + v * 36 + ch * 4) = pb[0];
        }
        __syncthreads();
        // --- mma over 4 k16 steps ---
#pragma unroll
        for (int k16 = 0; k16 < 4; k16++) {
            const int kof = k16 * 8;  // in u32 units
            uint32_t a[4][4], b[4][2];
            const uint32_t* ap = (const uint32_t*)As;
            const uint32_t* bp = (const uint32_t*)Bs;
#pragma unroll
            for (int mt = 0; mt < 4; mt++) {
                int r = mt * 16 + g;
                a[mt][0] = ap[r * 36 + kof + t];
                a[mt][1] = ap[(r + 8) * 36 + kof + t];
                a[mt][2] = ap[r * 36 + kof + t + 4];
                a[mt][3] = ap[(r + 8) * 36 + kof + t + 4];
            }
#pragma unroll
            for (int nt = 0; nt < 4; nt++) {
                int n = w * 32 + nt * 8 + g;
                b[nt][0] = bp[n * 36 + kof + t];
                b[nt][1] = bp[n * 36 + kof + t + 4];
            }
#pragma unroll
            for (int mt = 0; mt < 4; mt++)
#pragma unroll
                for (int nt = 0; nt < 4; nt++) mma16816(acc[mt][nt], a[mt], b[nt]);
        }
        __syncthreads();
    }
    // --- write split-K partials ---
    float* op = g_simp + ((size_t)(kc * F_ + f) * B_) * V_;
#pragma unroll
    for (int mt = 0; mt < 4; mt++) {
        int r = mt * 16 + g;
#pragma unroll
        for (int nt = 0; nt < 4; nt++) {
            int c = w * 32 + nt * 8 + 2 * t;
            *(float2*)&op[(size_t)r * V_ + c]       = make_float2(acc[mt][nt][0], acc[mt][nt][1]);
            *(float2*)&op[(size_t)(r + 8) * V_ + c] = make_float2(acc[mt][nt][2], acc[mt][nt][3]);
        }
    }
}

// ---------------- reduce partials, emit exact bf16 split of sim ----------------
__global__ void k_reduce() {
    int i = blockIdx.x * blockDim.x + threadIdx.x;  // F_*B_*V_ = 65536
    float s = 0.f;
#pragma unroll
    for (int kc = 0; kc < KCH; kc++) s += g_simp[(size_t)kc * (F_ * B_ * V_) + i];
    g_sim[i] = s;
    int si = (int)s;                       // exact integer
    g_Ah[i] = __float2bfloat16((float)(si & ~127));  // multiple of 128, |.|<=16384 -> exact bf16
    g_Al[i] = __float2bfloat16((float)(si & 127));   // 0..127 -> exact bf16
}

// ---------------- stage 3: est[b,f,d] = sign( sum_v sim[f,b,v]*cb[f,v,d] ) ----------------
__global__ void __launch_bounds__(256) k_update() {
    __shared__ __align__(16) __nv_bfloat16 Bs[128 * 72];
    __shared__ __align__(16) __nv_bfloat16 Ahs[64 * 72];
    __shared__ __align__(16) __nv_bfloat16 Als[64 * 72];
    const int dt = blockIdx.x, f = blockIdx.y;
    const int d0 = dt * 128;
    const int tid = threadIdx.x;
    const int w = tid >> 5, lane = tid & 31, g = lane >> 2, t = lane & 3;
    const int arow = tid >> 2, aseg = tid & 3;

    float acc[4][2][4];
#pragma unroll
    for (int mt = 0; mt < 4; mt++)
#pragma unroll
        for (int nt = 0; nt < 2; nt++)
#pragma unroll
            for (int j = 0; j < 4; j++) acc[mt][nt][j] = 0.f;

    for (int vs = 0; vs < 4; vs++) {
        const int v0 = vs * 64;
        {   // A tiles (hi / lo split of sim)
            int vv = v0 + aseg * 16;
            const uint4* ph = (const uint4*)(g_Ah + ((size_t)f * B_ + arow) * V_ + vv);
            const uint4* pl = (const uint4*)(g_Al + ((size_t)f * B_ + arow) * V_ + vv);
            uint4* ah = (uint4*)((uint32_t*)Ahs + arow * 36 + aseg * 8);
            uint4* al = (uint4*)((uint32_t*)Als + arow * 36 + aseg * 8);
            ah[0] = ph[0]; ah[1] = ph[1];
            al[0] = pl[0]; al[1] = pl[1];
        }
#pragma unroll
        for (int p = 0; p < 4; p++) {   // B tile (128 d x 64 v)
            int dl = p * 32 + (tid >> 3); int ch = tid & 7;
            const uint4* pb = (const uint4*)(g_cbD + ((size_t)(f * D_ + d0 + dl)) * V_ + v0 + ch * 8);
            *(uint4*)((uint32_t*)Bs + dl * 36 + ch * 4) = pb[0];
        }
        __syncthreads();
#pragma unroll
        for (int k16 = 0; k16 < 4; k16++) {
            const int kof = k16 * 8;
            uint32_t fa[4][4], fl[4][4], b[2][2];
            const uint32_t* ap = (const uint32_t*)Ahs;
            const uint32_t* lp = (const uint32_t*)Als;
            const uint32_t* bp = (const uint32_t*)Bs;
#pragma unroll
            for (int mt = 0; mt < 4; mt++) {
                int r = mt * 16 + g;
                fa[mt][0] = ap[r * 36 + kof + t];       fa[mt][1] = ap[(r + 8) * 36 + kof + t];
                fa[mt][2] = ap[r * 36 + kof + t + 4];   fa[mt][3] = ap[(r + 8) * 36 + kof + t + 4];
                fl[mt][0] = lp[r * 36 + kof + t];       fl[mt][1] = lp[(r + 8) * 36 + kof + t];
                fl[mt][2] = lp[r * 36 + kof + t + 4];   fl[mt][3] = lp[(r + 8) * 36 + kof + t + 4];
            }
#pragma unroll
            for (int nt = 0; nt < 2; nt++) {
                int n = w * 16 + nt * 8 + g;
                b[nt][0] = bp[n * 36 + kof + t];
                b[nt][1] = bp[n * 36 + kof + t + 4];
            }
#pragma unroll
            for (int mt = 0; mt < 4; mt++)
#pragma unroll
                for (int nt = 0; nt < 2; nt++) {
                    mma16816(acc[mt][nt], fa[mt], b[nt]);
                    mma16816(acc[mt][nt], fl[mt], b[nt]);
                }
        }
        __syncthreads();
    }
    // epilogue: sign(acc) -> +-1 bf16 into g_est_bf  (acc is exact integer; >=0 -> +1)
#pragma unroll
    for (int mt = 0; mt < 4; mt++) {
        int r = mt * 16 + g;
#pragma unroll
        for (int nt = 0; nt < 2; nt++) {
            int d = d0 + w * 16 + nt * 8 + 2 * t;
            uint32_t s0 = __float_as_uint(acc[mt][nt][0]);
            uint32_t s1 = __float_as_uint(acc[mt][nt][1]);
            uint32_t s2 = __float_as_uint(acc[mt][nt][2]);
            uint32_t s3 = __float_as_uint(acc[mt][nt][3]);
            uint32_t w0 = 0x3F803F80u | ((s0 >> 16) & 0x8000u) | (s1 & 0x80000000u);
            uint32_t w1 = 0x3F803F80u | ((s2 >> 16) & 0x8000u) | (s3 & 0x80000000u);
            ((uint32_t*)g_est_bf)[(((size_t)r * F_ + f) * D_ + d) >> 1] = w0;
            ((uint32_t*)g_est_bf)[(((size_t)(r + 8) * F_ + f) * D_ + d) >> 1] = w1;
        }
    }
}

// ---------------- outputs ----------------
__global__ void k_emit(float* __restrict__ out) {
    int i = blockIdx.x * blockDim.x + threadIdx.x;
    if (i >= B_ * F_ * D_ / 2) return;
    uint32_t w = ((const uint32_t*)g_est_bf)[i];
    float2 o;
    o.x = (w & 0x8000u) ? -1.f : 1.f;
    o.y = (w & 0x80000000u) ? -1.f : 1.f;
    ((float2*)out)[i] = o;
}

__global__ void k_outcome(float* __restrict__ out) {
    int warp = (blockIdx.x * blockDim.x + threadIdx.x) >> 5;
    int lane = threadIdx.x & 31;
    if (warp >= B_ * F_) return;
    int b = warp >> 2, f = warp & 3;
    const float* s = g_sim + ((size_t)(f * B_ + b)) * V_;
    float best = -1.f; int bi = 0;
#pragma unroll
    for (int j = 0; j < 8; j++) {
        int v = j * 32 + lane;
        float a = fabsf(s[v]);
        if (a > best) { best = a; bi = v; }     // ascending v: strict > keeps first
    }
#pragma unroll
    for (int off = 16; off; off >>= 1) {
        float ob = __shfl_down_sync(0xffffffffu, best, off);
        int   oi = __shfl_down_sync(0xffffffffu, bi, off);
        if (ob > best || (ob == best && oi < bi)) { best = ob; bi = oi; }
    }
    if (lane == 0) out[warp] = (float)bi;       // outcome[b][f], first-max index
}

// ---------------- host launch ----------------
extern "C" void kernel_launch(void* const* d_in, const int* in_sizes, int n_in,
                              void* d_out, int out_size) {
    const float *input = nullptr, *est0 = nullptr, *cb = nullptr;
    for (int i = 0; i < n_in; i++) {
        if      (in_sizes[i] == B_ * D_)        input = (const float*)d_in[i];
        else if (in_sizes[i] == B_ * F_ * D_)   est0  = (const float*)d_in[i];
        else if (in_sizes[i] == F_ * V_ * D_)   cb    = (const float*)d_in[i];
    }
    if (!input && n_in > 0) input = (const float*)d_in[0];
    if (!est0  && n_in > 1) est0  = (const float*)d_in[1];
    if (!cb    && n_in > 2) cb    = (const float*)d_in[2];

    // convert all inputs to +-1 bf16 (and transposed codebook layout)
    { int n = B_ * D_ / 2;        k_sign_pairs<<<(n + 255) / 256, 256>>>(input, 0, n); }
    { int n = B_ * F_ * D_ / 2;   k_sign_pairs<<<(n + 255) / 256, 256>>>(est0, 1, n); }
    { int n = F_ * V_ * D_ / 2;   k_sign_pairs<<<(n + 255) / 256, 256>>>(cb, 2, n); }
    k_trans<<<dim3(D_ / 32, V_ / 32, F_), 256>>>(cb);

    for (int it = 0; it < ITERS_; it++) {
        k_totalbf<<<B_ * D_ / 8 / 256, 256>>>();
        k_sim<<<dim3(KCH, F_), 256>>>(0);
        k_reduce<<<(F_ * B_ * V_) / 256, 256>>>();
        k_update<<<dim3(D_ / 128, F_), 256>>>();
    }
    // final similarity on converged estimates
    k_sim<<<dim3(KCH, F_), 256>>>(1);
    k_reduce<<<(F_ * B_ * V_) / 256, 256>>>();

    float* out = (float*)d_out;
    { int n = (B_ * F_ * D_ / 2 + 255) / 256; k_emit<<<n, 256>>>(out); }
    if (out_size >= B_ * F_ * D_ + B_ * F_) {
        k_outcome<<<32, 256>>>(out + (size_t)B_ * F_ * D_);
    }
}

// round 7
// speedup vs baseline: 1.1799x; 1.1799x over previous
#include <cuda_runtime.h>
#include <cuda_bf16.h>
#include <stdint.h>

#define B_ 64
#define F_ 4
#define V_ 256
#define D_ 16384
#define ITERS_ 10
#define KCH 32               // split-K chunks for stage 2
#define KC (D_/KCH)          // 512 k per chunk

// ---------------- static device scratch (no runtime allocation) ----------------
__device__ __align__(16) __nv_bfloat16 g_in_bf [B_*D_];                 // input, +-1 bf16
__device__ __align__(16) __nv_bfloat16 g_est_bf[B_*F_*D_];              // current estimates, +-1 bf16
__device__ __align__(16) __nv_bfloat16 g_T_bf  [B_*D_];                 // input * prod_f est (+-1 bf16)
__device__ __align__(16) __nv_bfloat16 g_cbK   [(size_t)F_*V_*D_];      // codebook [f][v][d] bf16
__device__ __align__(16) __nv_bfloat16 g_cbD   [(size_t)F_*D_*V_];      // codebook [f][d][v] bf16 (transposed)
__device__ __align__(16) float         g_simp  [(size_t)KCH*F_*B_*V_];  // split-K partials
__device__ __align__(16) float         g_sim   [F_*B_*V_];              // reduced sim (exact ints)
__device__ __align__(16) __nv_bfloat16 g_Ah    [F_*B_*V_];              // sim & ~127 (exact in bf16)
__device__ __align__(16) __nv_bfloat16 g_Al    [F_*B_*V_];              // sim &  127 (exact in bf16)

// ---------------- mma.sync helper (bf16, fp32 accum — exact for our integer data) ----
__device__ __forceinline__ void mma16816(float c[4], const uint32_t a[4], const uint32_t b[2]) {
    asm volatile(
        "mma.sync.aligned.m16n8k16.row.col.f32.bf16.bf16.f32 "
        "{%0,%1,%2,%3},{%4,%5,%6,%7},{%8,%9},{%0,%1,%2,%3};\n"
        : "+f"(c[0]), "+f"(c[1]), "+f"(c[2]), "+f"(c[3])
        : "r"(a[0]), "r"(a[1]), "r"(a[2]), "r"(a[3]), "r"(b[0]), "r"(b[1]));
}

// ldmatrix x4: four 8x8 b16 tiles; address groups lanes 0-7,8-15,16-23,24-31 -> r0..r3
__device__ __forceinline__ void ldsm_x4(uint32_t& r0, uint32_t& r1, uint32_t& r2, uint32_t& r3,
                                        uint32_t saddr) {
    asm volatile("ldmatrix.sync.aligned.m8n8.x4.shared.b16 {%0,%1,%2,%3}, [%4];"
                 : "=r"(r0), "=r"(r1), "=r"(r2), "=r"(r3) : "r"(saddr));
}

// ---------------- conversion kernels (run every launch; deterministic) ----------------
__global__ void k_sign_pairs(const float* __restrict__ src, int which, int npairs) {
    int i = blockIdx.x * blockDim.x + threadIdx.x;
    if (i >= npairs) return;
    uint2 u = ((const uint2*)src)[i];
    uint32_t w = 0x3F803F80u | ((u.x >> 16) & 0x8000u) | (u.y & 0x80000000u);
    uint32_t* dst = (which == 0) ? (uint32_t*)g_in_bf
                  : (which == 1) ? (uint32_t*)g_est_bf
                                 : (uint32_t*)g_cbK;
    dst[i] = w;
}

__global__ void k_trans(const float* __restrict__ cb) {
    __shared__ unsigned short ts[32][33];
    int f = blockIdx.z, d0 = blockIdx.x * 32, v0 = blockIdx.y * 32;
    int tx = threadIdx.x & 31, ty = threadIdx.x >> 5;  // 32 x 8
#pragma unroll
    for (int r = 0; r < 4; r++) {
        int v = v0 + ty + r * 8;
        uint32_t ub = __float_as_uint(cb[((size_t)(f * V_ + v)) * D_ + d0 + tx]);
        ts[ty + r * 8][tx] = (unsigned short)(0x3F80u | ((ub >> 16) & 0x8000u));
    }
    __syncthreads();
#pragma unroll
    for (int r = 0; r < 4; r++) {
        int d = d0 + ty + r * 8;
        ((unsigned short*)g_cbD)[((size_t)(f * D_ + d)) * V_ + v0 + tx] = ts[tx][ty + r * 8];
    }
}

// ---------------- per-iter: T = input * est0 * est1 * est2 * est3 (bf16 XOR) -----------
__global__ void k_totalbf() {
    int i = blockIdx.x * blockDim.x + threadIdx.x;     // uint4 over B_*D_ bf16 elements
    int e0 = i * 8;
    int b = e0 / D_, d = e0 % D_;
    uint4 t = *(const uint4*)(g_in_bf + (size_t)b * D_ + d);
#pragma unroll
    for (int ff = 0; ff < F_; ff++) {
        uint4 e = *(const uint4*)(g_est_bf + ((size_t)b * F_ + ff) * D_ + d);
        t.x ^= e.x; t.y ^= e.y; t.z ^= e.z; t.w ^= e.w;
    }
    *(uint4*)(g_T_bf + (size_t)b * D_ + d) = t;
}

// ---------------- stage 2: sim[f][b][v] = sum_d n[b,f,d] * cb[f,v,d] --------------------
// mode 0: n = T ^ est_f; mode 1: n = est_f.  Register-prefetch pipelined + ldmatrix.
__global__ void __launch_bounds__(256) k_sim(int mode) {
    __shared__ __align__(16) __nv_bfloat16 As[64 * 72];
    __shared__ __align__(16) __nv_bfloat16 Bs[256 * 72];
    const int kc = blockIdx.x, f = blockIdx.y;
    const int tid = threadIdx.x;
    const int w = tid >> 5, lane = tid & 31, g = lane >> 2, t = lane & 3;
    const int arow = tid >> 2, aseg = tid & 3;
    const int vB = tid >> 3, chB = tid & 7;

    const uint4* pe = (const uint4*)(g_est_bf + ((size_t)arow * F_ + f) * D_);
    const uint4* pt = (const uint4*)(g_T_bf + (size_t)arow * D_);

    const uint32_t asBase = (uint32_t)__cvta_generic_to_shared(As);
    const uint32_t bsBase = (uint32_t)__cvta_generic_to_shared(Bs);
    const int laneRow  = lane & 15;
    const int laneColH = (lane >> 4) & 1;     // 0/1 -> +8 bf16 columns

    float acc[4][4][4];
#pragma unroll
    for (int mt = 0; mt < 4; mt++)
#pragma unroll
        for (int nt = 0; nt < 4; nt++)
#pragma unroll
            for (int j = 0; j < 4; j++) acc[mt][nt][j] = 0.f;

    uint4 e0, e1, t0, t1;                      // A prefetch regs
    uint4 rB[8];                               // B prefetch regs
    t0 = make_uint4(0, 0, 0, 0); t1 = t0;

    // preload ks=0
    {
        const int k0 = kc * KC;
        int ai = (k0 >> 3) + aseg * 2;         // uint4 index (8 bf16 per uint4)
        e0 = pe[ai]; e1 = pe[ai + 1];
        if (mode == 0) { t0 = pt[ai]; t1 = pt[ai + 1]; }
#pragma unroll
        for (int p = 0; p < 8; p++) {
            int v = p * 32 + vB;
            rB[p] = *(const uint4*)(g_cbK + ((size_t)(f * V_ + v)) * D_ + k0 + chB * 8);
        }
    }

    for (int ks = 0; ks < KC / 64; ks++) {
        // ---- store current tile from regs ----
        {
            uint4 o0, o1;
            if (mode == 0) {
                o0.x = 0x3F803F80u ^ (e0.x ^ t0.x); o0.y = 0x3F803F80u ^ (e0.y ^ t0.y);
                o0.z = 0x3F803F80u ^ (e0.z ^ t0.z); o0.w = 0x3F803F80u ^ (e0.w ^ t0.w);
                o1.x = 0x3F803F80u ^ (e1.x ^ t1.x); o1.y = 0x3F803F80u ^ (e1.y ^ t1.y);
                o1.z = 0x3F803F80u ^ (e1.z ^ t1.z); o1.w = 0x3F803F80u ^ (e1.w ^ t1.w);
            } else { o0 = e0; o1 = e1; }
            uint4* as = (uint4*)((uint32_t*)As + arow * 36 + aseg * 8);
            as[0] = o0; as[1] = o1;
#pragma unroll
            for (int p = 0; p < 8; p++)
                *(uint4*)((uint32_t*)Bs + (p * 32 + vB) * 36 + chB * 4) = rB[p];
        }
        __syncthreads();

        // ---- prefetch next tile (overlapped with mma below) ----
        if (ks + 1 < KC / 64) {
            const int k0n = kc * KC + (ks + 1) * 64;
            int ai = (k0n >> 3) + aseg * 2;
            e0 = pe[ai]; e1 = pe[ai + 1];
            if (mode == 0) { t0 = pt[ai]; t1 = pt[ai + 1]; }
#pragma unroll
            for (int p = 0; p < 8; p++) {
                int v = p * 32 + vB;
                rB[p] = *(const uint4*)(g_cbK + ((size_t)(f * V_ + v)) * D_ + k0n + chB * 8);
            }
        }

        // ---- mma over 4 k16 steps (ldmatrix fragments) ----
#pragma unroll
        for (int k16 = 0; k16 < 4; k16++) {
            const int colElem = k16 * 16 + laneColH * 8;
            uint32_t a[4][4], b[4][2];
#pragma unroll
            for (int mt = 0; mt < 4; mt++) {
                uint32_t ad = asBase + ((mt * 16 + laneRow) * 72 + colElem) * 2;
                ldsm_x4(a[mt][0], a[mt][1], a[mt][2], a[mt][3], ad);
            }
#pragma unroll
            for (int h = 0; h < 2; h++) {
                uint32_t bd = bsBase + ((w * 32 + h * 16 + laneRow) * 72 + colElem) * 2;
                ldsm_x4(b[2 * h][0], b[2 * h + 1][0], b[2 * h][1], b[2 * h + 1][1], bd);
            }
#pragma unroll
            for (int mt = 0; mt < 4; mt++)
#pragma unroll
                for (int nt = 0; nt < 4; nt++) mma16816(acc[mt][nt], a[mt], b[nt]);
        }
        __syncthreads();
    }
    // --- write split-K partials ---
    float* op = g_simp + ((size_t)(kc * F_ + f) * B_) * V_;
#pragma unroll
    for (int mt = 0; mt < 4; mt++) {
        int r = mt * 16 + g;
#pragma unroll
        for (int nt = 0; nt < 4; nt++) {
            int c = w * 32 + nt * 8 + 2 * t;
            *(float2*)&op[(size_t)r * V_ + c]       = make_float2(acc[mt][nt][0], acc[mt][nt][1]);
            *(float2*)&op[(size_t)(r + 8) * V_ + c] = make_float2(acc[mt][nt][2], acc[mt][nt][3]);
        }
    }
}

// ---------------- reduce partials, emit exact bf16 split of sim ----------------
__global__ void k_reduce() {
    int i = blockIdx.x * blockDim.x + threadIdx.x;  // F_*B_*V_ = 65536
    float s = 0.f;
#pragma unroll
    for (int kc = 0; kc < KCH; kc++) s += g_simp[(size_t)kc * (F_ * B_ * V_) + i];
    g_sim[i] = s;
    int si = (int)s;                       // exact integer
    g_Ah[i] = __float2bfloat16((float)(si & ~127));  // multiple of 128 -> exact bf16
    g_Al[i] = __float2bfloat16((float)(si & 127));   // 0..127 -> exact bf16
}

// ---------------- stage 3: est[b,f,d] = sign( sum_v sim[f,b,v]*cb[f,v,d] ) --------------
// Register-prefetch pipelined + ldmatrix; fragment semantics identical to proven version.
__global__ void __launch_bounds__(256) k_update() {
    __shared__ __align__(16) __nv_bfloat16 Bs[128 * 72];
    __shared__ __align__(16) __nv_bfloat16 Ahs[64 * 72];
    __shared__ __align__(16) __nv_bfloat16 Als[64 * 72];
    const int dt = blockIdx.x, f = blockIdx.y;
    const int d0 = dt * 128;
    const int tid = threadIdx.x;
    const int w = tid >> 5, lane = tid & 31, g = lane >> 2, t = lane & 3;
    const int arow = tid >> 2, aseg = tid & 3;
    const int dB = tid >> 3, chB = tid & 7;

    const uint32_t ahBase = (uint32_t)__cvta_generic_to_shared(Ahs);
    const uint32_t alBase = (uint32_t)__cvta_generic_to_shared(Als);
    const uint32_t bsBase = (uint32_t)__cvta_generic_to_shared(Bs);
    const int laneRow  = lane & 15;
    const int laneColH = (lane >> 4) & 1;

    float acc[4][2][4];
#pragma unroll
    for (int mt = 0; mt < 4; mt++)
#pragma unroll
        for (int nt = 0; nt < 2; nt++)
#pragma unroll
            for (int j = 0; j < 4; j++) acc[mt][nt][j] = 0.f;

    uint4 h0, h1, l0, l1;       // A prefetch (hi/lo)
    uint4 rB[4];                // B prefetch

    // preload vs=0
    {
        const int vv = aseg * 16;
        h0 = *(const uint4*)(g_Ah + ((size_t)f * B_ + arow) * V_ + vv);
        h1 = *(const uint4*)(g_Ah + ((size_t)f * B_ + arow) * V_ + vv + 8);
        l0 = *(const uint4*)(g_Al + ((size_t)f * B_ + arow) * V_ + vv);
        l1 = *(const uint4*)(g_Al + ((size_t)f * B_ + arow) * V_ + vv + 8);
#pragma unroll
        for (int p = 0; p < 4; p++) {
            int dl = p * 32 + dB;
            rB[p] = *(const uint4*)(g_cbD + ((size_t)(f * D_ + d0 + dl)) * V_ + chB * 8);
        }
    }

    for (int vs = 0; vs < 4; vs++) {
        {   // store current tiles
            uint4* ah = (uint4*)((uint32_t*)Ahs + arow * 36 + aseg * 8);
            uint4* al = (uint4*)((uint32_t*)Als + arow * 36 + aseg * 8);
            ah[0] = h0; ah[1] = h1;
            al[0] = l0; al[1] = l1;
#pragma unroll
            for (int p = 0; p < 4; p++)
                *(uint4*)((uint32_t*)Bs + (p * 32 + dB) * 36 + chB * 4) = rB[p];
        }
        __syncthreads();

        if (vs + 1 < 4) {   // prefetch next chunk
            const int v0n = (vs + 1) * 64;
            const int vv = v0n + aseg * 16;
            h0 = *(const uint4*)(g_Ah + ((size_t)f * B_ + arow) * V_ + vv);
            h1 = *(const uint4*)(g_Ah + ((size_t)f * B_ + arow) * V_ + vv + 8);
            l0 = *(const uint4*)(g_Al + ((size_t)f * B_ + arow) * V_ + vv);
            l1 = *(const uint4*)(g_Al + ((size_t)f * B_ + arow) * V_ + vv + 8);
#pragma unroll
            for (int p = 0; p < 4; p++) {
                int dl = p * 32 + dB;
                rB[p] = *(const uint4*)(g_cbD + ((size_t)(f * D_ + d0 + dl)) * V_ + v0n + chB * 8);
            }
        }

#pragma unroll
        for (int k16 = 0; k16 < 4; k16++) {
            const int colElem = k16 * 16 + laneColH * 8;
            uint32_t fa[4][4], fl[4][4], b[2][2];
#pragma unroll
            for (int mt = 0; mt < 4; mt++) {
                uint32_t adh = ahBase + ((mt * 16 + laneRow) * 72 + colElem) * 2;
                uint32_t adl = alBase + ((mt * 16 + laneRow) * 72 + colElem) * 2;
                ldsm_x4(fa[mt][0], fa[mt][1], fa[mt][2], fa[mt][3], adh);
                ldsm_x4(fl[mt][0], fl[mt][1], fl[mt][2], fl[mt][3], adl);
            }
            {
                uint32_t bd = bsBase + ((w * 16 + laneRow) * 72 + colElem) * 2;
                ldsm_x4(b[0][0], b[1][0], b[0][1], b[1][1], bd);
            }
#pragma unroll
            for (int mt = 0; mt < 4; mt++)
#pragma unroll
                for (int nt = 0; nt < 2; nt++) {
                    mma16816(acc[mt][nt], fa[mt], b[nt]);
                    mma16816(acc[mt][nt], fl[mt], b[nt]);
                }
        }
        __syncthreads();
    }
    // epilogue: sign(acc) -> +-1 bf16 into g_est_bf  (acc is exact integer; >=0 -> +1)
#pragma unroll
    for (int mt = 0; mt < 4; mt++) {
        int r = mt * 16 + g;
#pragma unroll
        for (int nt = 0; nt < 2; nt++) {
            int d = d0 + w * 16 + nt * 8 + 2 * t;
            uint32_t s0 = __float_as_uint(acc[mt][nt][0]);
            uint32_t s1 = __float_as_uint(acc[mt][nt][1]);
            uint32_t s2 = __float_as_uint(acc[mt][nt][2]);
            uint32_t s3 = __float_as_uint(acc[mt][nt][3]);
            uint32_t w0 = 0x3F803F80u | ((s0 >> 16) & 0x8000u) | (s1 & 0x80000000u);
            uint32_t w1 = 0x3F803F80u | ((s2 >> 16) & 0x8000u) | (s3 & 0x80000000u);
            ((uint32_t*)g_est_bf)[(((size_t)r * F_ + f) * D_ + d) >> 1] = w0;
            ((uint32_t*)g_est_bf)[(((size_t)(r + 8) * F_ + f) * D_ + d) >> 1] = w1;
        }
    }
}

// ---------------- outputs ----------------
__global__ void k_emit(float* __restrict__ out) {
    int i = blockIdx.x * blockDim.x + threadIdx.x;
    if (i >= B_ * F_ * D_ / 2) return;
    uint32_t w = ((const uint32_t*)g_est_bf)[i];
    float2 o;
    o.x = (w & 0x8000u) ? -1.f : 1.f;
    o.y = (w & 0x80000000u) ? -1.f : 1.f;
    ((float2*)out)[i] = o;
}

__global__ void k_outcome(float* __restrict__ out) {
    int warp = (blockIdx.x * blockDim.x + threadIdx.x) >> 5;
    int lane = threadIdx.x & 31;
    if (warp >= B_ * F_) return;
    int b = warp >> 2, f = warp & 3;
    const float* s = g_sim + ((size_t)(f * B_ + b)) * V_;
    float best = -1.f; int bi = 0;
#pragma unroll
    for (int j = 0; j < 8; j++) {
        int v = j * 32 + lane;
        float a = fabsf(s[v]);
        if (a > best) { best = a; bi = v; }     // ascending v: strict > keeps first
    }
#pragma unroll
    for (int off = 16; off; off >>= 1) {
        float ob = __shfl_down_sync(0xffffffffu, best, off);
        int   oi = __shfl_down_sync(0xffffffffu, bi, off);
        if (ob > best || (ob == best && oi < bi)) { best = ob; bi = oi; }
    }
    if (lane == 0) out[warp] = (float)bi;       // outcome[b][f], first-max index
}

// ---------------- host launch ----------------
extern "C" void kernel_launch(void* const* d_in, const int* in_sizes, int n_in,
                              void* d_out, int out_size) {
    const float *input = nullptr, *est0 = nullptr, *cb = nullptr;
    for (int i = 0; i < n_in; i++) {
        if      (in_sizes[i] == B_ * D_)        input = (const float*)d_in[i];
        else if (in_sizes[i] == B_ * F_ * D_)   est0  = (const float*)d_in[i];
        else if (in_sizes[i] == F_ * V_ * D_)   cb    = (const float*)d_in[i];
    }
    if (!input && n_in > 0) input = (const float*)d_in[0];
    if (!est0  && n_in > 1) est0  = (const float*)d_in[1];
    if (!cb    && n_in > 2) cb    = (const float*)d_in[2];

    // convert all inputs to +-1 bf16 (and transposed codebook layout)
    { int n = B_ * D_ / 2;        k_sign_pairs<<<(n + 255) / 256, 256>>>(input, 0, n); }
    { int n = B_ * F_ * D_ / 2;   k_sign_pairs<<<(n + 255) / 256, 256>>>(est0, 1, n); }
    { int n = F_ * V_ * D_ / 2;   k_sign_pairs<<<(n + 255) / 256, 256>>>(cb, 2, n); }
    k_trans<<<dim3(D_ / 32, V_ / 32, F_), 256>>>(cb);

    for (int it = 0; it < ITERS_; it++) {
        k_totalbf<<<B_ * D_ / 8 / 256, 256>>>();
        k_sim<<<dim3(KCH, F_), 256>>>(0);
        k_reduce<<<(F_ * B_ * V_) / 256, 256>>>();
        k_update<<<dim3(D_ / 128, F_), 256>>>();
    }
    // final similarity on converged estimates
    k_sim<<<dim3(KCH, F_), 256>>>(1);
    k_reduce<<<(F_ * B_ * V_) / 256, 256>>>();

    float* out = (float*)d_out;
    { int n = (B_ * F_ * D_ / 2 + 255) / 256; k_emit<<<n, 256>>>(out); }
    if (out_size >= B_ * F_ * D_ + B_ * F_) {
        k_outcome<<<32, 256>>>(out + (size_t)B_ * F_ * D_);
    }
}